// round 2
// baseline (speedup 1.0000x reference)
#include <cuda_runtime.h>

#define BB 2
#define SS 2048
#define HH 768
#define NH 12
#define DD 64
#define BH (BB*NH)                 // 24
#define M_PROJ (BB*SS)             // 4096
#define OUT_ELEMS (BB*SS*HH)       // 3145728
#define ATTN_ELEMS ((size_t)BB*NH*SS*SS) // 100663296
#define NEGV (-1e32f)

#define KT_STRIDE 260   // 256 cols + 4 pad (16B aligned rows)
#define VT_STRIDE 68    // 64 d + 4 pad (16B aligned rows)

// ---- scratch (device globals: no allocation allowed) ----
__device__ float g_qh[BB*NH*SS*DD];     // [B,H,S,D]
__device__ float g_kh[BB*NH*SS*DD];
__device__ float g_vh[BB*NH*SS*DD];
__device__ float g_ctx[BB*SS*HH];       // merged heads [B,S,H*D]
__device__ float g_attn_scratch[BB*NH*SS*SS]; // fallback if attn not in d_out

// ============================================================
// Kernel 1: fused QKV projections (64x64x16 tiles, float4 LDS).
// ============================================================
__global__ void proj_qkv_kernel(const float* __restrict__ q,
                                const float* __restrict__ k,
                                const float* __restrict__ v,
                                const float* __restrict__ Wq, const float* __restrict__ bq,
                                const float* __restrict__ Wk, const float* __restrict__ bk,
                                const float* __restrict__ Wv, const float* __restrict__ bv) {
    const float* X; const float* W; const float* bias; float* Y;
    if (blockIdx.z == 0)      { X = q; W = Wq; bias = bq; Y = g_qh; }
    else if (blockIdx.z == 1) { X = k; W = Wk; bias = bk; Y = g_kh; }
    else                      { X = v; W = Wv; bias = bv; Y = g_vh; }

    __shared__ float As[16][68];
    __shared__ float Bs[16][68];
    int tid = threadIdx.x;
    int tx = tid & 15, ty = tid >> 4;
    int m0 = blockIdx.y * 64, n0 = blockIdx.x * 64;

    float acc[4][4] = {};
    for (int k0 = 0; k0 < HH; k0 += 16) {
        #pragma unroll
        for (int i = 0; i < 4; i++) {
            int idx = tid + 256 * i;
            int r = idx >> 4, c = idx & 15;
            As[c][r] = X[(size_t)(m0 + r) * HH + k0 + c];
            Bs[c][r] = W[(size_t)(n0 + r) * HH + k0 + c];
        }
        __syncthreads();
        #pragma unroll
        for (int kk = 0; kk < 16; kk++) {
            float4 a4 = *(const float4*)&As[kk][ty * 4];
            float4 b4 = *(const float4*)&Bs[kk][tx * 4];
            float a[4] = {a4.x, a4.y, a4.z, a4.w};
            float b[4] = {b4.x, b4.y, b4.z, b4.w};
            #pragma unroll
            for (int i = 0; i < 4; i++)
                #pragma unroll
                for (int j = 0; j < 4; j++) acc[i][j] = fmaf(a[i], b[j], acc[i][j]);
        }
        __syncthreads();
    }
    #pragma unroll
    for (int i = 0; i < 4; i++) {
        int m = m0 + ty * 4 + i;
        int b_idx = m / SS, s = m % SS;
        #pragma unroll
        for (int j = 0; j < 4; j++) {
            int n = n0 + tx * 4 + j;
            int h = n >> 6, d = n & 63;
            Y[(((size_t)b_idx * NH + h) * SS + s) * DD + d] = acc[i][j] + bias[n];
        }
    }
}

// ============================================================
// Fused attention: scores + mask + softmax + AV in one kernel.
// Block = (bh, 16-row tile). 512 threads, 16 warps, 1 CTA/SM.
// smem: sc[16][2048] (128KB) + qs + bias + kt/vt chunk union.
// ============================================================
__global__ void __launch_bounds__(512, 1)
fused_attn_kernel(const int* __restrict__ mask, float* __restrict__ attn) {
    extern __shared__ float smem[];
    float* sc   = smem;                  // 16*2048
    float* qs   = sc + 16 * 2048;        // 16*64
    float* bias = qs + 16 * 64;          // 2048
    float* ktv  = bias + 2048;           // max(64*260, 256*68) = 17408
    float* red  = sc;                    // aliases sc after phase 3 compute

    const int bh = blockIdx.y;
    const int b = bh / NH, h = bh % NH;
    const int m0 = blockIdx.x * 16;
    const int tid = threadIdx.x;
    const int w = tid >> 5, lane = tid & 31;

    const float* qh_head = g_qh + (size_t)bh * SS * DD;
    const float* kh_head = g_kh + (size_t)bh * SS * DD;
    const float* vh_head = g_vh + (size_t)bh * SS * DD;

    // ---- preload Q tile (contiguous) + mask bias ----
    for (int i = tid; i < 16 * 64; i += 512) qs[i] = qh_head[(size_t)m0 * 64 + i];
    for (int i = tid; i < 2048; i += 512)   bias[i] = mask[b * SS + i] ? NEGV : 0.0f;
    __syncthreads();

    const int rg = w & 3, rowbase = rg * 4;

    // =================== Phase 1: raw scores ===================
    {
        const int cpos = w >> 2;              // 0..3, 64 cols each
        const int dg = lane >> 3;             // 4-way d-split in warp
        const int slot = lane & 7;
        const int cb = cpos * 64 + slot * 4;  // local col (first half), +32 second

        for (int c0 = 0; c0 < SS; c0 += 256) {
            // load K chunk transposed: kt[d][c_local]
            {
                int cl = tid & 255, dh2 = tid >> 8;
                const float* src = kh_head + (size_t)(c0 + cl) * 64 + dh2 * 32;
                #pragma unroll
                for (int i = 0; i < 8; i++) {
                    float4 v4 = *(const float4*)(src + i * 4);
                    int d = dh2 * 32 + i * 4;
                    ktv[(d + 0) * KT_STRIDE + cl] = v4.x;
                    ktv[(d + 1) * KT_STRIDE + cl] = v4.y;
                    ktv[(d + 2) * KT_STRIDE + cl] = v4.z;
                    ktv[(d + 3) * KT_STRIDE + cl] = v4.w;
                }
            }
            __syncthreads();

            float acc[4][8] = {};
            #pragma unroll 4
            for (int t = 0; t < 16; t++) {
                int d = t * 4 + dg;
                float4 b0 = *(const float4*)&ktv[d * KT_STRIDE + cb];
                float4 b1 = *(const float4*)&ktv[d * KT_STRIDE + cb + 32];
                #pragma unroll
                for (int i = 0; i < 4; i++) {
                    float a = qs[(rowbase + i) * 64 + d];
                    acc[i][0] = fmaf(a, b0.x, acc[i][0]);
                    acc[i][1] = fmaf(a, b0.y, acc[i][1]);
                    acc[i][2] = fmaf(a, b0.z, acc[i][2]);
                    acc[i][3] = fmaf(a, b0.w, acc[i][3]);
                    acc[i][4] = fmaf(a, b1.x, acc[i][4]);
                    acc[i][5] = fmaf(a, b1.y, acc[i][5]);
                    acc[i][6] = fmaf(a, b1.z, acc[i][6]);
                    acc[i][7] = fmaf(a, b1.w, acc[i][7]);
                }
            }
            // reduce over dg (lane bits 3,4)
            #pragma unroll
            for (int i = 0; i < 4; i++)
                #pragma unroll
                for (int j = 0; j < 8; j++) {
                    float vv = acc[i][j];
                    vv += __shfl_xor_sync(0xFFFFFFFFu, vv, 8);
                    vv += __shfl_xor_sync(0xFFFFFFFFu, vv, 16);
                    acc[i][j] = vv;
                }
            if (dg == 0) {
                #pragma unroll
                for (int i = 0; i < 4; i++) {
                    float* dst = &sc[(rowbase + i) * 2048 + c0 + cb];
                    *(float4*)dst        = make_float4(acc[i][0], acc[i][1], acc[i][2], acc[i][3]);
                    *(float4*)(dst + 32) = make_float4(acc[i][4], acc[i][5], acc[i][6], acc[i][7]);
                }
            }
            __syncthreads();
        }
    }

    // =================== Phase 2: softmax (warp per row) ===================
    {
        float* p = sc + w * 2048;
        // pass A: scale + mask bias, track max
        float mx = -INFINITY;
        #pragma unroll
        for (int i = 0; i < 16; i++) {
            int c = i * 128 + lane * 4;
            float4 v4 = *(float4*)(p + c);
            float4 b4 = *(const float4*)(bias + c);
            v4.x = fmaf(v4.x, 0.125f, b4.x);
            v4.y = fmaf(v4.y, 0.125f, b4.y);
            v4.z = fmaf(v4.z, 0.125f, b4.z);
            v4.w = fmaf(v4.w, 0.125f, b4.w);
            *(float4*)(p + c) = v4;
            mx = fmaxf(mx, fmaxf(fmaxf(v4.x, v4.y), fmaxf(v4.z, v4.w)));
        }
        #pragma unroll
        for (int o = 16; o; o >>= 1) mx = fmaxf(mx, __shfl_xor_sync(0xFFFFFFFFu, mx, o));
        // pass B: exp + sum
        float sum = 0.0f;
        #pragma unroll
        for (int i = 0; i < 16; i++) {
            int c = i * 128 + lane * 4;
            float4 v4 = *(float4*)(p + c);
            v4.x = __expf(v4.x - mx);
            v4.y = __expf(v4.y - mx);
            v4.z = __expf(v4.z - mx);
            v4.w = __expf(v4.w - mx);
            *(float4*)(p + c) = v4;
            sum += v4.x + v4.y + v4.z + v4.w;
        }
        #pragma unroll
        for (int o = 16; o; o >>= 1) sum += __shfl_xor_sync(0xFFFFFFFFu, sum, o);
        float inv = 1.0f / sum;
        // pass C: normalize, write to sc (for AV) + attn gmem
        float* arow = attn + ((size_t)bh * SS + m0 + w) * SS;
        #pragma unroll
        for (int i = 0; i < 16; i++) {
            int c = i * 128 + lane * 4;
            float4 v4 = *(float4*)(p + c);
            v4.x *= inv; v4.y *= inv; v4.z *= inv; v4.w *= inv;
            *(float4*)(p + c) = v4;
            *(float4*)(arow + c) = v4;
        }
    }
    __syncthreads();

    // =================== Phase 3: ctx = P @ V ===================
    {
        const int kgh = w >> 2;
        const int kgl = lane >> 3, dslot = lane & 7;
        const int kid = kgh * 4 + kgl;   // 0..15 interleaved k-split

        float acc[4][8] = {};
        for (int cb0 = 0; cb0 < SS; cb0 += 256) {
            // load V chunk: vt[k_local][d]
            {
                int kl = tid & 255, dh2 = tid >> 8;
                const float* src = vh_head + (size_t)(cb0 + kl) * 64 + dh2 * 32;
                #pragma unroll
                for (int i = 0; i < 8; i++) {
                    float4 v4 = *(const float4*)(src + i * 4);
                    *(float4*)&ktv[kl * VT_STRIDE + dh2 * 32 + i * 4] = v4;
                }
            }
            __syncthreads();
            #pragma unroll 4
            for (int t = 0; t < 16; t++) {
                int kl = t * 16 + kid;
                float4 b0 = *(const float4*)&ktv[kl * VT_STRIDE + dslot * 4];
                float4 b1 = *(const float4*)&ktv[kl * VT_STRIDE + dslot * 4 + 32];
                int kgk = cb0 + kl;
                #pragma unroll
                for (int i = 0; i < 4; i++) {
                    float a = sc[(rowbase + i) * 2048 + kgk];
                    acc[i][0] = fmaf(a, b0.x, acc[i][0]);
                    acc[i][1] = fmaf(a, b0.y, acc[i][1]);
                    acc[i][2] = fmaf(a, b0.z, acc[i][2]);
                    acc[i][3] = fmaf(a, b0.w, acc[i][3]);
                    acc[i][4] = fmaf(a, b1.x, acc[i][4]);
                    acc[i][5] = fmaf(a, b1.y, acc[i][5]);
                    acc[i][6] = fmaf(a, b1.z, acc[i][6]);
                    acc[i][7] = fmaf(a, b1.w, acc[i][7]);
                }
            }
            __syncthreads();
        }
        // reduce over kgl (lane bits 3,4)
        #pragma unroll
        for (int i = 0; i < 4; i++)
            #pragma unroll
            for (int j = 0; j < 8; j++) {
                float vv = acc[i][j];
                vv += __shfl_xor_sync(0xFFFFFFFFu, vv, 8);
                vv += __shfl_xor_sync(0xFFFFFFFFu, vv, 16);
                acc[i][j] = vv;
            }
        // partials across kgh groups into red (aliases sc; safe post-barrier)
        if (kgl == 0) {
            #pragma unroll
            for (int i = 0; i < 4; i++) {
                int base = kgh * 1024 + (rowbase + i) * 64 + dslot * 4;
                *(float4*)&red[base]      = make_float4(acc[i][0], acc[i][1], acc[i][2], acc[i][3]);
                *(float4*)&red[base + 32] = make_float4(acc[i][4], acc[i][5], acc[i][6], acc[i][7]);
            }
        }
        __syncthreads();
        // final sum over 4 kgh groups, write ctx
        {
            int o = tid * 2;             // 1024 outputs, 2 per thread
            int row = o >> 6, d = o & 63;
            float2 s = make_float2(0.f, 0.f);
            #pragma unroll
            for (int kg = 0; kg < 4; kg++) {
                float2 v2 = *(const float2*)&red[kg * 1024 + row * 64 + d];
                s.x += v2.x; s.y += v2.y;
            }
            *(float2*)&g_ctx[((size_t)(b * SS + m0 + row)) * HH + h * 64 + d] = s;
        }
    }
}

// ============================================================
// Kernel 5: out = ctx @ Wm^T + bm (float4 LDS version).
// ============================================================
__global__ void out_proj_kernel(const float* __restrict__ Wm,
                                const float* __restrict__ bm,
                                float* __restrict__ out) {
    __shared__ float As[16][68];
    __shared__ float Bs[16][68];
    int tid = threadIdx.x;
    int tx = tid & 15, ty = tid >> 4;
    int m0 = blockIdx.y * 64, n0 = blockIdx.x * 64;

    float acc[4][4] = {};
    for (int k0 = 0; k0 < HH; k0 += 16) {
        #pragma unroll
        for (int i = 0; i < 4; i++) {
            int idx = tid + 256 * i;
            int r = idx >> 4, c = idx & 15;
            As[c][r] = g_ctx[(size_t)(m0 + r) * HH + k0 + c];
            Bs[c][r] = Wm[(size_t)(n0 + r) * HH + k0 + c];
        }
        __syncthreads();
        #pragma unroll
        for (int kk = 0; kk < 16; kk++) {
            float4 a4 = *(const float4*)&As[kk][ty * 4];
            float4 b4 = *(const float4*)&Bs[kk][tx * 4];
            float a[4] = {a4.x, a4.y, a4.z, a4.w};
            float b[4] = {b4.x, b4.y, b4.z, b4.w};
            #pragma unroll
            for (int i = 0; i < 4; i++)
                #pragma unroll
                for (int j = 0; j < 4; j++) acc[i][j] = fmaf(a[i], b[j], acc[i][j]);
        }
        __syncthreads();
    }
    #pragma unroll
    for (int i = 0; i < 4; i++) {
        int m = m0 + ty * 4 + i;
        #pragma unroll
        for (int j = 0; j < 4; j++) {
            int n = n0 + tx * 4 + j;
            out[(size_t)m * HH + n] = acc[i][j] + bm[n];
        }
    }
}

// ============================================================
// Host launcher
// ============================================================
extern "C" void kernel_launch(void* const* d_in, const int* in_sizes, int n_in,
                              void* d_out, int out_size) {
    const float* v    = (const float*)d_in[0];
    const float* k    = (const float*)d_in[1];
    const float* q    = (const float*)d_in[2];
    const int*   mask = (const int*)  d_in[3];
    const float* Wv   = (const float*)d_in[4];
    const float* bv   = (const float*)d_in[5];
    const float* Wk   = (const float*)d_in[6];
    const float* bk   = (const float*)d_in[7];
    const float* Wq   = (const float*)d_in[8];
    const float* bq   = (const float*)d_in[9];
    const float* Wm   = (const float*)d_in[10];
    const float* bm   = (const float*)d_in[11];
    float* out = (float*)d_out;

    float* attn;
    if ((size_t)out_size >= (size_t)OUT_ELEMS + ATTN_ELEMS) {
        attn = out + OUT_ELEMS;
    } else {
        void* p = nullptr;
        cudaGetSymbolAddress(&p, g_attn_scratch);
        attn = (float*)p;
    }

    static int smem_set = 0;
    const int SMEM_BYTES = (16 * 2048 + 16 * 64 + 2048 + 17408) * 4;  // 212992
    if (!smem_set) {
        cudaFuncSetAttribute(fused_attn_kernel,
                             cudaFuncAttributeMaxDynamicSharedMemorySize, SMEM_BYTES);
        smem_set = 1;
    }

    proj_qkv_kernel<<<dim3(HH / 64, M_PROJ / 64, 3), 256>>>(q, k, v, Wq, bq, Wk, bk, Wv, bv);
    fused_attn_kernel<<<dim3(SS / 16, BH), 512, SMEM_BYTES>>>(mask, attn);
    out_proj_kernel<<<dim3(HH / 64, M_PROJ / 64, 1), 256>>>(Wm, bm, out);
}

// round 3
// speedup vs baseline: 2.3611x; 2.3611x over previous
#include <cuda_runtime.h>
#include <mma.h>
using namespace nvcuda;

#define BB 2
#define SS 2048
#define HH 768
#define NH 12
#define DD 64
#define BH (BB*NH)                 // 24
#define M_PROJ (BB*SS)             // 4096
#define OUT_ELEMS (BB*SS*HH)       // 3145728
#define ATTN_ELEMS ((size_t)BB*NH*SS*SS) // 100663296
#define NEGV (-1e32f)

// ---- scratch (device globals: no allocation allowed) ----
__device__ float g_qh[BB*NH*SS*DD];     // [B,H,S,D]
__device__ float g_kh[BB*NH*SS*DD];
__device__ float g_vh[BB*NH*SS*DD];
__device__ float g_ctx[BB*SS*HH];       // merged heads [B,S,H*D]
__device__ float g_attn_scratch[BB*NH*SS*SS]; // fallback if attn not in d_out

typedef wmma::fragment<wmma::matrix_a, 16, 16, 8, wmma::precision::tf32, wmma::row_major> FragA;
typedef wmma::fragment<wmma::matrix_b, 16, 16, 8, wmma::precision::tf32, wmma::col_major> FragBc;
typedef wmma::fragment<wmma::matrix_b, 16, 16, 8, wmma::precision::tf32, wmma::row_major> FragBr;
typedef wmma::fragment<wmma::accumulator, 16, 16, 8, float> FragC;

#define LDT 20   // smem tile stride (16 k + 4 pad)
#define LDC 68   // smem C stride (64 + 4 pad)

// ============================================================
// Kernel 1: fused QKV projections, tf32 wmma.
// Y = X @ W^T + b, head-split output. M=4096 N=768 K=768.
// Block 256 thr (8 warps), tile 128x64, warp 32x32.
// ============================================================
__global__ void __launch_bounds__(256)
proj_qkv_kernel(const float* __restrict__ q,
                const float* __restrict__ k,
                const float* __restrict__ v,
                const float* __restrict__ Wq, const float* __restrict__ bq,
                const float* __restrict__ Wk, const float* __restrict__ bk,
                const float* __restrict__ Wv, const float* __restrict__ bv) {
    const float* X; const float* W; const float* bias; float* Y;
    if (blockIdx.z == 0)      { X = q; W = Wq; bias = bq; Y = g_qh; }
    else if (blockIdx.z == 1) { X = k; W = Wk; bias = bk; Y = g_kh; }
    else                      { X = v; W = Wv; bias = bv; Y = g_vh; }

    __shared__ float sbuf[128 * LDC];   // 34.8KB; As+Bs overlay then Cs
    __shared__ float bias_s[64];
    float* As = sbuf;                 // [128][LDT]
    float* Bs = sbuf + 128 * LDT;     // [64][LDT]
    float* Cs = sbuf;                 // [128][LDC] (reused after mainloop)

    const int tid = threadIdx.x;
    const int w = tid >> 5;
    const int m0 = blockIdx.y * 128, n0 = blockIdx.x * 64;
    const int mw = (w >> 1) * 32, nw = (w & 1) * 32;
    if (tid < 64) bias_s[tid] = bias[n0 + tid];

    FragC acc[2][2];
    #pragma unroll
    for (int i = 0; i < 2; i++)
        #pragma unroll
        for (int j = 0; j < 2; j++) wmma::fill_fragment(acc[i][j], 0.0f);

    for (int k0 = 0; k0 < HH; k0 += 16) {
        #pragma unroll
        for (int jj = 0; jj < 2; jj++) {
            int e = tid + 256 * jj;
            int r = e >> 2, c4 = (e & 3) * 4;
            float4 t4 = *(const float4*)&X[(size_t)(m0 + r) * HH + k0 + c4];
            t4.x = wmma::__float_to_tf32(t4.x); t4.y = wmma::__float_to_tf32(t4.y);
            t4.z = wmma::__float_to_tf32(t4.z); t4.w = wmma::__float_to_tf32(t4.w);
            *(float4*)&As[r * LDT + c4] = t4;
        }
        {
            int r = tid >> 2, c4 = (tid & 3) * 4;
            float4 t4 = *(const float4*)&W[(size_t)(n0 + r) * HH + k0 + c4];
            t4.x = wmma::__float_to_tf32(t4.x); t4.y = wmma::__float_to_tf32(t4.y);
            t4.z = wmma::__float_to_tf32(t4.z); t4.w = wmma::__float_to_tf32(t4.w);
            *(float4*)&Bs[r * LDT + c4] = t4;
        }
        __syncthreads();
        #pragma unroll
        for (int kt = 0; kt < 2; kt++) {
            FragA a0, a1; FragBc b0, b1;
            wmma::load_matrix_sync(a0, &As[(mw +  0) * LDT + kt * 8], LDT);
            wmma::load_matrix_sync(a1, &As[(mw + 16) * LDT + kt * 8], LDT);
            wmma::load_matrix_sync(b0, &Bs[(nw +  0) * LDT + kt * 8], LDT);
            wmma::load_matrix_sync(b1, &Bs[(nw + 16) * LDT + kt * 8], LDT);
            wmma::mma_sync(acc[0][0], a0, b0, acc[0][0]);
            wmma::mma_sync(acc[0][1], a0, b1, acc[0][1]);
            wmma::mma_sync(acc[1][0], a1, b0, acc[1][0]);
            wmma::mma_sync(acc[1][1], a1, b1, acc[1][1]);
        }
        __syncthreads();
    }
    #pragma unroll
    for (int i = 0; i < 2; i++)
        #pragma unroll
        for (int j = 0; j < 2; j++)
            wmma::store_matrix_sync(&Cs[(mw + i * 16) * LDC + nw + j * 16], acc[i][j], LDC, wmma::mem_row_major);
    __syncthreads();

    const int h = n0 >> 6;
    #pragma unroll
    for (int jj = 0; jj < 8; jj++) {
        int e = tid + 256 * jj;
        int r = e >> 4, c4 = (e & 15) * 4;
        float4 t4 = *(float4*)&Cs[r * LDC + c4];
        t4.x += bias_s[c4]; t4.y += bias_s[c4 + 1];
        t4.z += bias_s[c4 + 2]; t4.w += bias_s[c4 + 3];
        int m = m0 + r, b = m >> 11, s = m & 2047;
        *(float4*)&Y[(((size_t)b * NH + h) * SS + s) * DD + c4] = t4;
    }
}

// ============================================================
// Kernel 2: raw scores = (qh @ kh^T) * 0.125, tf32 wmma.
// Per (b,h): M=N=2048, K=64. Block 256 thr, tile 128x64.
// Direct frag store to attn buffer (no mask here).
// ============================================================
__global__ void __launch_bounds__(256)
scores_kernel(float* __restrict__ attn) {
    const int bh = blockIdx.z;
    const float* A = g_qh + (size_t)bh * SS * DD;
    const float* B = g_kh + (size_t)bh * SS * DD;

    __shared__ float As[128 * LDT];
    __shared__ float Bs[64 * LDT];

    const int tid = threadIdx.x;
    const int w = tid >> 5;
    const int m0 = blockIdx.y * 128, n0 = blockIdx.x * 64;
    const int mw = (w >> 1) * 32, nw = (w & 1) * 32;

    FragC acc[2][2];
    #pragma unroll
    for (int i = 0; i < 2; i++)
        #pragma unroll
        for (int j = 0; j < 2; j++) wmma::fill_fragment(acc[i][j], 0.0f);

    for (int k0 = 0; k0 < DD; k0 += 16) {
        #pragma unroll
        for (int jj = 0; jj < 2; jj++) {
            int e = tid + 256 * jj;
            int r = e >> 2, c4 = (e & 3) * 4;
            float4 t4 = *(const float4*)&A[(size_t)(m0 + r) * DD + k0 + c4];
            t4.x = wmma::__float_to_tf32(t4.x); t4.y = wmma::__float_to_tf32(t4.y);
            t4.z = wmma::__float_to_tf32(t4.z); t4.w = wmma::__float_to_tf32(t4.w);
            *(float4*)&As[r * LDT + c4] = t4;
        }
        {
            int r = tid >> 2, c4 = (tid & 3) * 4;
            float4 t4 = *(const float4*)&B[(size_t)(n0 + r) * DD + k0 + c4];
            t4.x = wmma::__float_to_tf32(t4.x); t4.y = wmma::__float_to_tf32(t4.y);
            t4.z = wmma::__float_to_tf32(t4.z); t4.w = wmma::__float_to_tf32(t4.w);
            *(float4*)&Bs[r * LDT + c4] = t4;
        }
        __syncthreads();
        #pragma unroll
        for (int kt = 0; kt < 2; kt++) {
            FragA a0, a1; FragBc b0, b1;
            wmma::load_matrix_sync(a0, &As[(mw +  0) * LDT + kt * 8], LDT);
            wmma::load_matrix_sync(a1, &As[(mw + 16) * LDT + kt * 8], LDT);
            wmma::load_matrix_sync(b0, &Bs[(nw +  0) * LDT + kt * 8], LDT);
            wmma::load_matrix_sync(b1, &Bs[(nw + 16) * LDT + kt * 8], LDT);
            wmma::mma_sync(acc[0][0], a0, b0, acc[0][0]);
            wmma::mma_sync(acc[0][1], a0, b1, acc[0][1]);
            wmma::mma_sync(acc[1][0], a1, b0, acc[1][0]);
            wmma::mma_sync(acc[1][1], a1, b1, acc[1][1]);
        }
        __syncthreads();
    }
    #pragma unroll
    for (int i = 0; i < 2; i++)
        #pragma unroll
        for (int j = 0; j < 2; j++) {
            #pragma unroll
            for (int t = 0; t < acc[i][j].num_elements; t++) acc[i][j].x[t] *= 0.125f;
            float* dst = attn + ((size_t)bh * SS + m0 + mw + i * 16) * SS + n0 + nw + j * 16;
            wmma::store_matrix_sync(dst, acc[i][j], SS, wmma::mem_row_major);
        }
}

// ============================================================
// Kernel 3: fused mask + softmax + AV. 16 rows per block, 256 thr.
// Reads raw scores from attn, writes normalized attn (fp32),
// keeps tf32 copy in smem, then P @ V with wmma (V chunks via L2).
// ============================================================
#define SC_LD 2052
__global__ void __launch_bounds__(256)
softmax_av_kernel(const int* __restrict__ mask, float* __restrict__ attn) {
    extern __shared__ float sm[];
    float* sc    = sm;                       // [16][2052] tf32 P
    float* Vs    = sm + 16 * SC_LD;          // [128][68]; later Cred [2][16][68]
    float* biasv = sm + 16 * SC_LD + 128 * LDC; // [2048]

    const int tid = threadIdx.x;
    const int w = tid >> 5, lane = tid & 31;
    const int bh = blockIdx.y;
    const int b = bh / NH, h = bh % NH;
    const int m0 = blockIdx.x * 16;
    const float* vh_head = g_vh + (size_t)bh * SS * DD;

    #pragma unroll
    for (int i = 0; i < 8; i++) {
        int c = tid + 256 * i;
        biasv[c] = mask[b * SS + c] ? NEGV : 0.0f;
    }
    __syncthreads();

    // ---- softmax: warp w owns rows 2w, 2w+1; row values in registers ----
    #pragma unroll
    for (int rr = 0; rr < 2; rr++) {
        int row = 2 * w + rr;
        float* arow = attn + ((size_t)bh * SS + m0 + row) * SS;
        float vreg[64];
        float mx = -INFINITY;
        #pragma unroll
        for (int i = 0; i < 16; i++) {
            int c = lane * 4 + i * 128;
            float4 t4 = *(const float4*)(arow + c);
            t4.x += biasv[c]; t4.y += biasv[c + 1];
            t4.z += biasv[c + 2]; t4.w += biasv[c + 3];
            vreg[i * 4 + 0] = t4.x; vreg[i * 4 + 1] = t4.y;
            vreg[i * 4 + 2] = t4.z; vreg[i * 4 + 3] = t4.w;
            mx = fmaxf(mx, fmaxf(fmaxf(t4.x, t4.y), fmaxf(t4.z, t4.w)));
        }
        #pragma unroll
        for (int o = 16; o; o >>= 1) mx = fmaxf(mx, __shfl_xor_sync(0xFFFFFFFFu, mx, o));
        float sum = 0.0f;
        #pragma unroll
        for (int i = 0; i < 64; i++) {
            vreg[i] = __expf(vreg[i] - mx);
            sum += vreg[i];
        }
        #pragma unroll
        for (int o = 16; o; o >>= 1) sum += __shfl_xor_sync(0xFFFFFFFFu, sum, o);
        float inv = 1.0f / sum;
        float* srow = sc + row * SC_LD;
        #pragma unroll
        for (int i = 0; i < 16; i++) {
            int c = lane * 4 + i * 128;
            float4 t4;
            t4.x = vreg[i * 4 + 0] * inv; t4.y = vreg[i * 4 + 1] * inv;
            t4.z = vreg[i * 4 + 2] * inv; t4.w = vreg[i * 4 + 3] * inv;
            *(float4*)(arow + c) = t4;                 // exact fp32 attn out
            t4.x = wmma::__float_to_tf32(t4.x); t4.y = wmma::__float_to_tf32(t4.y);
            t4.z = wmma::__float_to_tf32(t4.z); t4.w = wmma::__float_to_tf32(t4.w);
            *(float4*)(srow + c) = t4;                 // tf32 copy for MMA
        }
    }
    __syncthreads();

    // ---- AV: C[16][64] = P[16][2048] @ V[2048][64] ----
    const int nw = (w & 3) * 16;
    const int kg = w >> 2;            // 2-way k-split across warps
    FragC acc;
    wmma::fill_fragment(acc, 0.0f);

    for (int c0 = 0; c0 < SS; c0 += 128) {
        #pragma unroll
        for (int jj = 0; jj < 8; jj++) {
            int e = tid + 256 * jj;
            int kl = e >> 4, d4 = (e & 15) * 4;
            float4 t4 = *(const float4*)&vh_head[(size_t)(c0 + kl) * DD + d4];
            t4.x = wmma::__float_to_tf32(t4.x); t4.y = wmma::__float_to_tf32(t4.y);
            t4.z = wmma::__float_to_tf32(t4.z); t4.w = wmma::__float_to_tf32(t4.w);
            *(float4*)&Vs[kl * LDC + d4] = t4;
        }
        __syncthreads();
        #pragma unroll
        for (int ks = 0; ks < 8; ks++) {
            int kloc = kg * 64 + ks * 8;
            FragA a; FragBr bfr;
            wmma::load_matrix_sync(a, &sc[c0 + kloc], SC_LD);
            wmma::load_matrix_sync(bfr, &Vs[kloc * LDC + nw], LDC);
            wmma::mma_sync(acc, a, bfr, acc);
        }
        __syncthreads();
    }
    // reduce the 2 k-groups via smem (reuse Vs region)
    float* Cred = Vs;   // [2][16][LDC]
    wmma::store_matrix_sync(&Cred[(kg * 16) * LDC + nw], acc, LDC, wmma::mem_row_major);
    __syncthreads();
    {
        int r = tid >> 4, d4 = (tid & 15) * 4;
        float4 x0 = *(float4*)&Cred[r * LDC + d4];
        float4 x1 = *(float4*)&Cred[(16 + r) * LDC + d4];
        x0.x += x1.x; x0.y += x1.y; x0.z += x1.z; x0.w += x1.w;
        *(float4*)&g_ctx[((size_t)(b * SS + m0 + r)) * HH + h * 64 + d4] = x0;
    }
}

// ============================================================
// Kernel 4: out = ctx @ Wm^T + bm, tf32 wmma. Same shape as K1.
// ============================================================
__global__ void __launch_bounds__(256)
out_proj_kernel(const float* __restrict__ Wm,
                const float* __restrict__ bm,
                float* __restrict__ out) {
    __shared__ float sbuf[128 * LDC];
    __shared__ float bias_s[64];
    float* As = sbuf;
    float* Bs = sbuf + 128 * LDT;
    float* Cs = sbuf;

    const int tid = threadIdx.x;
    const int w = tid >> 5;
    const int m0 = blockIdx.y * 128, n0 = blockIdx.x * 64;
    const int mw = (w >> 1) * 32, nw = (w & 1) * 32;
    if (tid < 64) bias_s[tid] = bm[n0 + tid];

    FragC acc[2][2];
    #pragma unroll
    for (int i = 0; i < 2; i++)
        #pragma unroll
        for (int j = 0; j < 2; j++) wmma::fill_fragment(acc[i][j], 0.0f);

    for (int k0 = 0; k0 < HH; k0 += 16) {
        #pragma unroll
        for (int jj = 0; jj < 2; jj++) {
            int e = tid + 256 * jj;
            int r = e >> 2, c4 = (e & 3) * 4;
            float4 t4 = *(const float4*)&g_ctx[(size_t)(m0 + r) * HH + k0 + c4];
            t4.x = wmma::__float_to_tf32(t4.x); t4.y = wmma::__float_to_tf32(t4.y);
            t4.z = wmma::__float_to_tf32(t4.z); t4.w = wmma::__float_to_tf32(t4.w);
            *(float4*)&As[r * LDT + c4] = t4;
        }
        {
            int r = tid >> 2, c4 = (tid & 3) * 4;
            float4 t4 = *(const float4*)&Wm[(size_t)(n0 + r) * HH + k0 + c4];
            t4.x = wmma::__float_to_tf32(t4.x); t4.y = wmma::__float_to_tf32(t4.y);
            t4.z = wmma::__float_to_tf32(t4.z); t4.w = wmma::__float_to_tf32(t4.w);
            *(float4*)&Bs[r * LDT + c4] = t4;
        }
        __syncthreads();
        #pragma unroll
        for (int kt = 0; kt < 2; kt++) {
            FragA a0, a1; FragBc b0, b1;
            wmma::load_matrix_sync(a0, &As[(mw +  0) * LDT + kt * 8], LDT);
            wmma::load_matrix_sync(a1, &As[(mw + 16) * LDT + kt * 8], LDT);
            wmma::load_matrix_sync(b0, &Bs[(nw +  0) * LDT + kt * 8], LDT);
            wmma::load_matrix_sync(b1, &Bs[(nw + 16) * LDT + kt * 8], LDT);
            wmma::mma_sync(acc[0][0], a0, b0, acc[0][0]);
            wmma::mma_sync(acc[0][1], a0, b1, acc[0][1]);
            wmma::mma_sync(acc[1][0], a1, b0, acc[1][0]);
            wmma::mma_sync(acc[1][1], a1, b1, acc[1][1]);
        }
        __syncthreads();
    }
    #pragma unroll
    for (int i = 0; i < 2; i++)
        #pragma unroll
        for (int j = 0; j < 2; j++)
            wmma::store_matrix_sync(&Cs[(mw + i * 16) * LDC + nw + j * 16], acc[i][j], LDC, wmma::mem_row_major);
    __syncthreads();

    #pragma unroll
    for (int jj = 0; jj < 8; jj++) {
        int e = tid + 256 * jj;
        int r = e >> 4, c4 = (e & 15) * 4;
        float4 t4 = *(float4*)&Cs[r * LDC + c4];
        t4.x += bias_s[c4]; t4.y += bias_s[c4 + 1];
        t4.z += bias_s[c4 + 2]; t4.w += bias_s[c4 + 3];
        *(float4*)&out[(size_t)(m0 + r) * HH + n0 + c4] = t4;
    }
}

// ============================================================
// Host launcher
// ============================================================
extern "C" void kernel_launch(void* const* d_in, const int* in_sizes, int n_in,
                              void* d_out, int out_size) {
    const float* v    = (const float*)d_in[0];
    const float* k    = (const float*)d_in[1];
    const float* q    = (const float*)d_in[2];
    const int*   mask = (const int*)  d_in[3];
    const float* Wv   = (const float*)d_in[4];
    const float* bv   = (const float*)d_in[5];
    const float* Wk   = (const float*)d_in[6];
    const float* bk   = (const float*)d_in[7];
    const float* Wq   = (const float*)d_in[8];
    const float* bq   = (const float*)d_in[9];
    const float* Wm   = (const float*)d_in[10];
    const float* bm   = (const float*)d_in[11];
    float* out = (float*)d_out;

    float* attn;
    if ((size_t)out_size >= (size_t)OUT_ELEMS + ATTN_ELEMS) {
        attn = out + OUT_ELEMS;
    } else {
        void* p = nullptr;
        cudaGetSymbolAddress(&p, g_attn_scratch);
        attn = (float*)p;
    }

    const int SMEM_K3 = (16 * SC_LD + 128 * LDC + 2048) * 4;  // 174336 B
    static int smem_set = 0;
    if (!smem_set) {
        cudaFuncSetAttribute(softmax_av_kernel,
                             cudaFuncAttributeMaxDynamicSharedMemorySize, SMEM_K3);
        smem_set = 1;
    }

    proj_qkv_kernel<<<dim3(HH / 64, M_PROJ / 128, 3), 256>>>(q, k, v, Wq, bq, Wk, bk, Wv, bv);
    scores_kernel<<<dim3(SS / 64, SS / 128, BH), 256>>>(attn);
    softmax_av_kernel<<<dim3(SS / 16, BH), 256, SMEM_K3>>>(mask, attn);
    out_proj_kernel<<<dim3(HH / 64, M_PROJ / 128, 1), 256>>>(Wm, bm, out);
}

// round 4
// speedup vs baseline: 2.3663x; 1.0022x over previous
#include <cuda_runtime.h>
#include <mma.h>
using namespace nvcuda;

#define BB 2
#define SS 2048
#define HH 768
#define NH 12
#define DD 64
#define BH (BB*NH)                 // 24
#define M_PROJ (BB*SS)             // 4096
#define OUT_ELEMS (BB*SS*HH)       // 3145728
#define ATTN_ELEMS ((size_t)BB*NH*SS*SS) // 100663296
#define NEGV (-1e32f)

// ---- scratch (device globals: no allocation allowed) ----
__device__ float g_qh[BB*NH*SS*DD];     // [B,H,S,D]
__device__ float g_kh[BB*NH*SS*DD];
__device__ float g_vh[BB*NH*SS*DD];
__device__ float g_ctx[BB*SS*HH];       // merged heads [B,S,H*D]
__device__ float g_linv[BH*SS];         // per-row 1/sum for attn rescale
__device__ float g_attn_scratch[BB*NH*SS*SS]; // fallback if attn not in d_out

typedef wmma::fragment<wmma::matrix_a, 16, 16, 8, wmma::precision::tf32, wmma::row_major> FragA;
typedef wmma::fragment<wmma::matrix_b, 16, 16, 8, wmma::precision::tf32, wmma::col_major> FragBc;
typedef wmma::fragment<wmma::matrix_b, 16, 16, 8, wmma::precision::tf32, wmma::row_major> FragBr;
typedef wmma::fragment<wmma::accumulator, 16, 16, 8, float> FragC;

#define LDT 20   // proj smem tile stride
#define LDC 68   // smem C / chunk stride (64 + 4 pad)

// ============================================================
// Kernel 1: fused QKV projections, tf32 wmma (unchanged from R3).
// ============================================================
__global__ void __launch_bounds__(256)
proj_qkv_kernel(const float* __restrict__ q,
                const float* __restrict__ k,
                const float* __restrict__ v,
                const float* __restrict__ Wq, const float* __restrict__ bq,
                const float* __restrict__ Wk, const float* __restrict__ bk,
                const float* __restrict__ Wv, const float* __restrict__ bv) {
    const float* X; const float* W; const float* bias; float* Y;
    if (blockIdx.z == 0)      { X = q; W = Wq; bias = bq; Y = g_qh; }
    else if (blockIdx.z == 1) { X = k; W = Wk; bias = bk; Y = g_kh; }
    else                      { X = v; W = Wv; bias = bv; Y = g_vh; }

    __shared__ float sbuf[128 * LDC];
    __shared__ float bias_s[64];
    float* As = sbuf;
    float* Bs = sbuf + 128 * LDT;
    float* Cs = sbuf;

    const int tid = threadIdx.x;
    const int w = tid >> 5;
    const int m0 = blockIdx.y * 128, n0 = blockIdx.x * 64;
    const int mw = (w >> 1) * 32, nw = (w & 1) * 32;
    if (tid < 64) bias_s[tid] = bias[n0 + tid];

    FragC acc[2][2];
    #pragma unroll
    for (int i = 0; i < 2; i++)
        #pragma unroll
        for (int j = 0; j < 2; j++) wmma::fill_fragment(acc[i][j], 0.0f);

    for (int k0 = 0; k0 < HH; k0 += 16) {
        #pragma unroll
        for (int jj = 0; jj < 2; jj++) {
            int e = tid + 256 * jj;
            int r = e >> 2, c4 = (e & 3) * 4;
            float4 t4 = *(const float4*)&X[(size_t)(m0 + r) * HH + k0 + c4];
            t4.x = wmma::__float_to_tf32(t4.x); t4.y = wmma::__float_to_tf32(t4.y);
            t4.z = wmma::__float_to_tf32(t4.z); t4.w = wmma::__float_to_tf32(t4.w);
            *(float4*)&As[r * LDT + c4] = t4;
        }
        {
            int r = tid >> 2, c4 = (tid & 3) * 4;
            float4 t4 = *(const float4*)&W[(size_t)(n0 + r) * HH + k0 + c4];
            t4.x = wmma::__float_to_tf32(t4.x); t4.y = wmma::__float_to_tf32(t4.y);
            t4.z = wmma::__float_to_tf32(t4.z); t4.w = wmma::__float_to_tf32(t4.w);
            *(float4*)&Bs[r * LDT + c4] = t4;
        }
        __syncthreads();
        #pragma unroll
        for (int kt = 0; kt < 2; kt++) {
            FragA a0, a1; FragBc b0, b1;
            wmma::load_matrix_sync(a0, &As[(mw +  0) * LDT + kt * 8], LDT);
            wmma::load_matrix_sync(a1, &As[(mw + 16) * LDT + kt * 8], LDT);
            wmma::load_matrix_sync(b0, &Bs[(nw +  0) * LDT + kt * 8], LDT);
            wmma::load_matrix_sync(b1, &Bs[(nw + 16) * LDT + kt * 8], LDT);
            wmma::mma_sync(acc[0][0], a0, b0, acc[0][0]);
            wmma::mma_sync(acc[0][1], a0, b1, acc[0][1]);
            wmma::mma_sync(acc[1][0], a1, b0, acc[1][0]);
            wmma::mma_sync(acc[1][1], a1, b1, acc[1][1]);
        }
        __syncthreads();
    }
    #pragma unroll
    for (int i = 0; i < 2; i++)
        #pragma unroll
        for (int j = 0; j < 2; j++)
            wmma::store_matrix_sync(&Cs[(mw + i * 16) * LDC + nw + j * 16], acc[i][j], LDC, wmma::mem_row_major);
    __syncthreads();

    const int h = n0 >> 6;
    #pragma unroll
    for (int jj = 0; jj < 8; jj++) {
        int e = tid + 256 * jj;
        int r = e >> 4, c4 = (e & 15) * 4;
        float4 t4 = *(float4*)&Cs[r * LDC + c4];
        t4.x += bias_s[c4]; t4.y += bias_s[c4 + 1];
        t4.z += bias_s[c4 + 2]; t4.w += bias_s[c4 + 3];
        int m = m0 + r, b = m >> 11, s = m & 2047;
        *(float4*)&Y[(((size_t)b * NH + h) * SS + s) * DD + c4] = t4;
    }
}

// ============================================================
// Kernel 2: fully fused attention (no-max softmax, deferred norm).
// CTA = 128 Q rows of one (b,h). Single pass over 32 K/V chunks:
//   S = Qs@Ks^T (wmma) -> p_u = exp(0.125*S + maskbias) ->
//   write p_u to attn (unnormalized), accumulate row sums,
//   AV += tf32(p_u) @ Vs (wmma, persistent accumulators).
// ctx normalized in-kernel; attn rescaled by kernel 3.
// ============================================================
__global__ void __launch_bounds__(256, 2)
fused_attn_kernel(const int* __restrict__ mask, float* __restrict__ attn) {
    extern __shared__ float sm[];
    float* Qs    = sm;                    // [128][LDC]
    float* Ks    = Qs + 128 * LDC;        // [64][LDC]
    float* Vs    = Ks + 64 * LDC;         // [64][LDC]
    float* ps    = Vs + 64 * LDC;         // [128][LDC]
    float* biasv = ps + 128 * LDC;        // [2048]

    const int tid = threadIdx.x;
    const int w = tid >> 5;
    const int bh = blockIdx.y;
    const int b = bh / NH, h = bh % NH;
    const int m0 = blockIdx.x * 128;
    const int wm = (w >> 1) * 32, wn = (w & 1) * 32;

    const float* qh_head = g_qh + (size_t)bh * SS * DD + (size_t)m0 * DD;
    const float* kh_head = g_kh + (size_t)bh * SS * DD;
    const float* vh_head = g_vh + (size_t)bh * SS * DD;

    // load Q tile (tf32) + mask bias
    #pragma unroll
    for (int jj = 0; jj < 2; jj++) {
        int e = tid + 256 * jj;
        int r = e >> 2, c16 = (e & 3) * 16;
        #pragma unroll
        for (int i = 0; i < 4; i++) {
            float4 t4 = *(const float4*)&qh_head[(size_t)r * DD + c16 + i * 4];
            t4.x = wmma::__float_to_tf32(t4.x); t4.y = wmma::__float_to_tf32(t4.y);
            t4.z = wmma::__float_to_tf32(t4.z); t4.w = wmma::__float_to_tf32(t4.w);
            *(float4*)&Qs[r * LDC + c16 + i * 4] = t4;
        }
    }
    #pragma unroll
    for (int i = 0; i < 8; i++) {
        int c = tid + 256 * i;
        biasv[c] = mask[b * SS + c] ? NEGV : 0.0f;
    }
    __syncthreads();

    const int sr  = tid >> 1;        // stats row 0..127 (this thread's row)
    const int sc0 = (tid & 1) * 32;  // column half within chunk
    float l_run = 0.0f;

    FragC accv[2][2];
    #pragma unroll
    for (int i = 0; i < 2; i++)
        #pragma unroll
        for (int j = 0; j < 2; j++) wmma::fill_fragment(accv[i][j], 0.0f);

    float* arow = attn + ((size_t)bh * SS + m0 + sr) * SS;

    for (int c0 = 0; c0 < SS; c0 += 64) {
        // ---- load K + V chunk (tf32) ----
        {
            int kr = tid >> 2, c16 = (tid & 3) * 16;
            const float* ksrc = kh_head + (size_t)(c0 + kr) * DD + c16;
            const float* vsrc = vh_head + (size_t)(c0 + kr) * DD + c16;
            #pragma unroll
            for (int i = 0; i < 4; i++) {
                float4 t4 = *(const float4*)(ksrc + i * 4);
                t4.x = wmma::__float_to_tf32(t4.x); t4.y = wmma::__float_to_tf32(t4.y);
                t4.z = wmma::__float_to_tf32(t4.z); t4.w = wmma::__float_to_tf32(t4.w);
                *(float4*)&Ks[kr * LDC + c16 + i * 4] = t4;
                float4 u4 = *(const float4*)(vsrc + i * 4);
                u4.x = wmma::__float_to_tf32(u4.x); u4.y = wmma::__float_to_tf32(u4.y);
                u4.z = wmma::__float_to_tf32(u4.z); u4.w = wmma::__float_to_tf32(u4.w);
                *(float4*)&Vs[kr * LDC + c16 + i * 4] = u4;
            }
        }
        __syncthreads();

        // ---- S = Q @ K^T (this 64-col chunk) ----
        {
            FragC acc[2][2];
            #pragma unroll
            for (int i = 0; i < 2; i++)
                #pragma unroll
                for (int j = 0; j < 2; j++) wmma::fill_fragment(acc[i][j], 0.0f);
            #pragma unroll
            for (int ks = 0; ks < 8; ks++) {
                FragA a0, a1; FragBc b0, b1;
                wmma::load_matrix_sync(a0, &Qs[(wm +  0) * LDC + ks * 8], LDC);
                wmma::load_matrix_sync(a1, &Qs[(wm + 16) * LDC + ks * 8], LDC);
                wmma::load_matrix_sync(b0, &Ks[(wn +  0) * LDC + ks * 8], LDC);
                wmma::load_matrix_sync(b1, &Ks[(wn + 16) * LDC + ks * 8], LDC);
                wmma::mma_sync(acc[0][0], a0, b0, acc[0][0]);
                wmma::mma_sync(acc[0][1], a0, b1, acc[0][1]);
                wmma::mma_sync(acc[1][0], a1, b0, acc[1][0]);
                wmma::mma_sync(acc[1][1], a1, b1, acc[1][1]);
            }
            #pragma unroll
            for (int i = 0; i < 2; i++)
                #pragma unroll
                for (int j = 0; j < 2; j++)
                    wmma::store_matrix_sync(&ps[(wm + i * 16) * LDC + wn + j * 16], acc[i][j], LDC, wmma::mem_row_major);
        }
        __syncthreads();

        // ---- p_u = exp(0.125*s + bias); attn write; tf32 back to ps ----
        {
            float lsum = 0.0f;
            #pragma unroll
            for (int i = 0; i < 8; i++) {
                int c = sc0 + i * 4;
                float4 t4 = *(float4*)&ps[sr * LDC + c];
                float4 b4 = *(const float4*)&biasv[c0 + c];
                float4 p4;
                p4.x = __expf(fmaf(t4.x, 0.125f, b4.x));
                p4.y = __expf(fmaf(t4.y, 0.125f, b4.y));
                p4.z = __expf(fmaf(t4.z, 0.125f, b4.z));
                p4.w = __expf(fmaf(t4.w, 0.125f, b4.w));
                lsum += p4.x + p4.y + p4.z + p4.w;
                *(float4*)&arow[c0 + c] = p4;   // unnormalized attn
                p4.x = wmma::__float_to_tf32(p4.x); p4.y = wmma::__float_to_tf32(p4.y);
                p4.z = wmma::__float_to_tf32(p4.z); p4.w = wmma::__float_to_tf32(p4.w);
                *(float4*)&ps[sr * LDC + c] = p4;
            }
            l_run += lsum;
        }
        __syncthreads();

        // ---- AV accumulate: accv += P(128x64) @ V(64x64) ----
        #pragma unroll
        for (int ks = 0; ks < 8; ks++) {
            FragA a0, a1; FragBr b0, b1;
            wmma::load_matrix_sync(a0, &ps[(wm +  0) * LDC + ks * 8], LDC);
            wmma::load_matrix_sync(a1, &ps[(wm + 16) * LDC + ks * 8], LDC);
            wmma::load_matrix_sync(b0, &Vs[(ks * 8) * LDC + wn +  0], LDC);
            wmma::load_matrix_sync(b1, &Vs[(ks * 8) * LDC + wn + 16], LDC);
            wmma::mma_sync(accv[0][0], a0, b0, accv[0][0]);
            wmma::mma_sync(accv[0][1], a0, b1, accv[0][1]);
            wmma::mma_sync(accv[1][0], a1, b0, accv[1][0]);
            wmma::mma_sync(accv[1][1], a1, b1, accv[1][1]);
        }
        __syncthreads();
    }

    // finalize row sum (pair-combine) and publish inverse
    l_run += __shfl_xor_sync(0xFFFFFFFFu, l_run, 1);
    float inv_l = 1.0f / l_run;
    if ((tid & 1) == 0) g_linv[bh * SS + m0 + sr] = inv_l;

    // store accv, normalize, write ctx
    #pragma unroll
    for (int i = 0; i < 2; i++)
        #pragma unroll
        for (int j = 0; j < 2; j++)
            wmma::store_matrix_sync(&ps[(wm + i * 16) * LDC + wn + j * 16], accv[i][j], LDC, wmma::mem_row_major);
    __syncthreads();
    {
        float* dst = &g_ctx[((size_t)(b * SS + m0 + sr)) * HH + h * 64 + sc0];
        #pragma unroll
        for (int i = 0; i < 8; i++) {
            float4 t4 = *(float4*)&ps[sr * LDC + sc0 + i * 4];
            t4.x *= inv_l; t4.y *= inv_l; t4.z *= inv_l; t4.w *= inv_l;
            *(float4*)&dst[i * 4] = t4;
        }
    }
}

// ============================================================
// Kernel 3: attn rescale (row-wise multiply by 1/sum). Streaming.
// ============================================================
__global__ void __launch_bounds__(256)
attn_scale_kernel(float* __restrict__ attn) {
    const int row = blockIdx.x;
    const float inv = g_linv[row];
    float* p = attn + (size_t)row * SS;
    const int t = threadIdx.x;
    #pragma unroll
    for (int i = 0; i < 2; i++) {
        int c = (t + i * 256) * 4;
        float4 v4 = *(float4*)&p[c];
        v4.x *= inv; v4.y *= inv; v4.z *= inv; v4.w *= inv;
        *(float4*)&p[c] = v4;
    }
}

// ============================================================
// Kernel 4: out = ctx @ Wm^T + bm (unchanged from R3).
// ============================================================
__global__ void __launch_bounds__(256)
out_proj_kernel(const float* __restrict__ Wm,
                const float* __restrict__ bm,
                float* __restrict__ out) {
    __shared__ float sbuf[128 * LDC];
    __shared__ float bias_s[64];
    float* As = sbuf;
    float* Bs = sbuf + 128 * LDT;
    float* Cs = sbuf;

    const int tid = threadIdx.x;
    const int w = tid >> 5;
    const int m0 = blockIdx.y * 128, n0 = blockIdx.x * 64;
    const int mw = (w >> 1) * 32, nw = (w & 1) * 32;
    if (tid < 64) bias_s[tid] = bm[n0 + tid];

    FragC acc[2][2];
    #pragma unroll
    for (int i = 0; i < 2; i++)
        #pragma unroll
        for (int j = 0; j < 2; j++) wmma::fill_fragment(acc[i][j], 0.0f);

    for (int k0 = 0; k0 < HH; k0 += 16) {
        #pragma unroll
        for (int jj = 0; jj < 2; jj++) {
            int e = tid + 256 * jj;
            int r = e >> 2, c4 = (e & 3) * 4;
            float4 t4 = *(const float4*)&g_ctx[(size_t)(m0 + r) * HH + k0 + c4];
            t4.x = wmma::__float_to_tf32(t4.x); t4.y = wmma::__float_to_tf32(t4.y);
            t4.z = wmma::__float_to_tf32(t4.z); t4.w = wmma::__float_to_tf32(t4.w);
            *(float4*)&As[r * LDT + c4] = t4;
        }
        {
            int r = tid >> 2, c4 = (tid & 3) * 4;
            float4 t4 = *(const float4*)&Wm[(size_t)(n0 + r) * HH + k0 + c4];
            t4.x = wmma::__float_to_tf32(t4.x); t4.y = wmma::__float_to_tf32(t4.y);
            t4.z = wmma::__float_to_tf32(t4.z); t4.w = wmma::__float_to_tf32(t4.w);
            *(float4*)&Bs[r * LDT + c4] = t4;
        }
        __syncthreads();
        #pragma unroll
        for (int kt = 0; kt < 2; kt++) {
            FragA a0, a1; FragBc b0, b1;
            wmma::load_matrix_sync(a0, &As[(mw +  0) * LDT + kt * 8], LDT);
            wmma::load_matrix_sync(a1, &As[(mw + 16) * LDT + kt * 8], LDT);
            wmma::load_matrix_sync(b0, &Bs[(nw +  0) * LDT + kt * 8], LDT);
            wmma::load_matrix_sync(b1, &Bs[(nw + 16) * LDT + kt * 8], LDT);
            wmma::mma_sync(acc[0][0], a0, b0, acc[0][0]);
            wmma::mma_sync(acc[0][1], a0, b1, acc[0][1]);
            wmma::mma_sync(acc[1][0], a1, b0, acc[1][0]);
            wmma::mma_sync(acc[1][1], a1, b1, acc[1][1]);
        }
        __syncthreads();
    }
    #pragma unroll
    for (int i = 0; i < 2; i++)
        #pragma unroll
        for (int j = 0; j < 2; j++)
            wmma::store_matrix_sync(&Cs[(mw + i * 16) * LDC + nw + j * 16], acc[i][j], LDC, wmma::mem_row_major);
    __syncthreads();

    #pragma unroll
    for (int jj = 0; jj < 8; jj++) {
        int e = tid + 256 * jj;
        int r = e >> 4, c4 = (e & 15) * 4;
        float4 t4 = *(float4*)&Cs[r * LDC + c4];
        t4.x += bias_s[c4]; t4.y += bias_s[c4 + 1];
        t4.z += bias_s[c4 + 2]; t4.w += bias_s[c4 + 3];
        *(float4*)&out[(size_t)(m0 + r) * HH + n0 + c4] = t4;
    }
}

// ============================================================
// Host launcher
// ============================================================
extern "C" void kernel_launch(void* const* d_in, const int* in_sizes, int n_in,
                              void* d_out, int out_size) {
    const float* v    = (const float*)d_in[0];
    const float* k    = (const float*)d_in[1];
    const float* q    = (const float*)d_in[2];
    const int*   mask = (const int*)  d_in[3];
    const float* Wv   = (const float*)d_in[4];
    const float* bv   = (const float*)d_in[5];
    const float* Wk   = (const float*)d_in[6];
    const float* bk   = (const float*)d_in[7];
    const float* Wq   = (const float*)d_in[8];
    const float* bq   = (const float*)d_in[9];
    const float* Wm   = (const float*)d_in[10];
    const float* bm   = (const float*)d_in[11];
    float* out = (float*)d_out;

    float* attn;
    if ((size_t)out_size >= (size_t)OUT_ELEMS + ATTN_ELEMS) {
        attn = out + OUT_ELEMS;
    } else {
        void* p = nullptr;
        cudaGetSymbolAddress(&p, g_attn_scratch);
        attn = (float*)p;
    }

    const int SMEM_FA = (128 * LDC + 64 * LDC + 64 * LDC + 128 * LDC + 2048) * 4; // 112640
    static int smem_set = 0;
    if (!smem_set) {
        cudaFuncSetAttribute(fused_attn_kernel,
                             cudaFuncAttributeMaxDynamicSharedMemorySize, SMEM_FA);
        smem_set = 1;
    }

    proj_qkv_kernel<<<dim3(HH / 64, M_PROJ / 128, 3), 256>>>(q, k, v, Wq, bq, Wk, bk, Wv, bv);
    fused_attn_kernel<<<dim3(SS / 128, BH), 256, SMEM_FA>>>(mask, attn);
    attn_scale_kernel<<<BH * SS, 256>>>(attn);
    out_proj_kernel<<<dim3(HH / 64, M_PROJ / 128, 1), 256>>>(Wm, bm, out);
}